// round 9
// baseline (speedup 1.0000x reference)
#include <cuda_runtime.h>
#include <math.h>
#include <stdint.h>

// MemoryUnit, Round 8: 2-CTA cluster per batch element.
// vs R7: (1) GEMM rebalance by matrix — group A (warps 0-3) owns the eg GEMM
// plus the serial chain, group B (warps 4-7) owns the wc GEMM + M update;
// both sides share the same accumulator registers and chunk code.
// (2) double-buffered prefetch in the GEMM and fu loops.

namespace {
constexpr int S_ = 2048;
constexpr int B_ = 64;
constexpr int D_ = 256;
constexpr int K_ = 16;
constexpr int NT = 256;
constexpr float EPSLN = 1e-5f;
constexpr float MOMC  = 0.9f;

__device__ __forceinline__ float geluf(float v) {
    return 0.5f * v * (1.0f + erff(v * 0.70710678118654752440f));
}
__device__ __forceinline__ float sigmf(float v) {
    return 1.0f / (1.0f + expf(-v));
}
__device__ __forceinline__ uint32_t smem_u32(const void* p) {
    return (uint32_t)__cvta_generic_to_shared(const_cast<void*>(p));
}
__device__ __forceinline__ uint32_t peer_addr(uint32_t la, uint32_t peer) {
    uint32_t ra;
    asm("mapa.shared::cluster.u32 %0, %1, %2;" : "=r"(ra) : "r"(la), "r"(peer));
    return ra;
}
__device__ __forceinline__ void st_peer_f32(uint32_t ra, float v) {
    asm volatile("st.shared::cluster.f32 [%0], %1;" :: "r"(ra), "f"(v) : "memory");
}
__device__ __forceinline__ void st_peer_f64(uint32_t ra, float a, float b) {
    asm volatile("st.shared::cluster.v2.f32 [%0], {%1,%2};"
                 :: "r"(ra), "f"(a), "f"(b) : "memory");
}
__device__ __forceinline__ void st_peer_f128(uint32_t ra, float4 v) {
    asm volatile("st.shared::cluster.v4.f32 [%0], {%1,%2,%3,%4};"
                 :: "r"(ra), "f"(v.x), "f"(v.y), "f"(v.z), "f"(v.w) : "memory");
}
__device__ __forceinline__ void cluster_sync_() {
    asm volatile("barrier.cluster.arrive.aligned;\n\t"
                 "barrier.cluster.wait.aligned;" ::: "memory");
}
__device__ __forceinline__ void barA() { asm volatile("bar.sync 1, 128;" ::: "memory"); }
__device__ __forceinline__ void barB() { asm volatile("bar.sync 2, 128;" ::: "memory"); }
__device__ __forceinline__ float2 ld2(const float* p) {
    return *reinterpret_cast<const float2*>(p);
}
} // namespace

__global__ __launch_bounds__(NT, 1) __cluster_dims__(2, 1, 1)
void memunit_kernel(
    const float* __restrict__ x,     const float* __restrict__ slot_init,
    const float* __restrict__ Wq,    const float* __restrict__ bq,
    const float* __restrict__ Wk,    const float* __restrict__ bk,
    const float* __restrict__ Wv,    const float* __restrict__ bv,
    const float* __restrict__ wg1W,  const float* __restrict__ wg1b,
    const float* __restrict__ wg2W,  const float* __restrict__ wg2b,
    const float* __restrict__ egW,   const float* __restrict__ egb,
    const float* __restrict__ wcW,   const float* __restrict__ wcb,
    const float* __restrict__ wclng, const float* __restrict__ wclnb,
    const float* __restrict__ fuW,   const float* __restrict__ fub,
    const float* __restrict__ fulng, const float* __restrict__ fulnb,
    const float* __restrict__ ong,   const float* __restrict__ onb,
    float* __restrict__ out)
{
    __shared__ float sM[D_][K_];       // full M, feature-major, peer-mirrored
    __shared__ float scat[2 * D_];     // [x_t | r]
    __shared__ float sQ[D_];           // full q (with bias)
    __shared__ float sKv[128];         // Wk @ q for my CTA's 128 i-rows
    __shared__ float sMbar[D_];        // attn-weighted slot average
    __shared__ float sG[128][K_];      // gelu(write pre-act), local-o rows
    __shared__ float sE[128][K_];      // sigmoid(erase pre-act)
    __shared__ float sLP[4][K_];       // A: logit warp partials
    __shared__ float sGP[4][2 * K_];   // B: gstat warp partials
    __shared__ float sGloc[2 * K_], eG[2 * K_];
    __shared__ float sLoc[K_], eL[K_];
    __shared__ float sFB[64][4];       // B's fu/wg1 half partials
    __shared__ float sBR[4][3];
    __shared__ float sF[3], eF[3], sU[2], eU[2];
    __shared__ float sAttn[K_], sEvict[K_], sPers[K_], sMean[K_], sRstd[K_];
    __shared__ float sNov;

    const int tid  = threadIdx.x;
    const int lane = tid & 31;
    const int wid  = tid >> 5;
    const bool isA = tid < 128;
    const int gt   = tid & 127;
    const int ih   = gt & 1;           // i-half within 256
    const int op   = gt >> 1;          // o-pair 0..63
    uint32_t rank;
    asm("mov.u32 %0, %%cluster_ctarank;" : "=r"(rank));
    const uint32_t peer = rank ^ 1u;
    const int b  = blockIdx.x >> 1;
    const int og = (int)rank * 128 + op * 2;

    #pragma unroll
    for (int j = 0; j < K_; ++j) sM[tid][j] = slot_init[j * D_ + tid];
    if (tid < K_) sPers[tid] = 0.f;

    const float2 bqv = ld2(bq + og), bvv = ld2(bv + og);
    const float2 egbv = ld2(egb + og), wcbv = ld2(wcb + og);
    const float2 fubv = ld2(fub + og), fulngv = ld2(fulng + og), fulnbv = ld2(fulnb + og);
    const float2 wg1bv = ld2(wg1b + og), wg2wv = ld2(wg2W + og);
    const float  wg2b0 = wg2b[0];
    const float2 ongv = ld2(ong + og), onbv = ld2(onb + og);
    const int   grow = (int)rank * 128 + gt;
    const float cgB = wclng[grow], cbB = wclnb[grow];

    // matrix split: A side computes eg, B side computes wc (same shape)
    const float* Wlo = isA ? egW : wcW;          // x-part rows [0,256)
    const float* Whi = Wlo + D_ * D_;            // slot-part rows [256,512)
    const float biasC0 = isA ? egbv.x : wcbv.x;  // per-side bias for own rows
    const float biasC1 = isA ? egbv.y : wcbv.y;
    __syncthreads();

    for (int t = 0; t < S_; ++t) {
        scat[tid] = x[((size_t)t * B_ + b) * D_ + tid];
        __syncthreads();

        // shared accumulators: A => eg, B => wc
        float accJ0[K_], accJ1[K_];
        float accC0 = 0.f, accC1 = 0.f;
        #pragma unroll
        for (int j = 0; j < K_; ++j) { accJ0[j] = 0.f; accJ1[j] = 0.f; }

        // double-buffered GEMM chunk over my i-half (i = (ih<<7)+c)
        auto gemm_chunk = [&](int c0, int c1) {
            const int i0 = ih << 7;
            float2 pL[4], pH[4];
            #pragma unroll
            for (int u = 0; u < 4; ++u) {
                const int lo = (i0 + c0 + u) * D_ + og;
                pL[u] = ld2(Wlo + lo);
                pH[u] = ld2(Whi + lo);
            }
            for (int c = c0; c < c1; c += 4) {
                float2 cL[4], cH[4];
                #pragma unroll
                for (int u = 0; u < 4; ++u) { cL[u] = pL[u]; cH[u] = pH[u]; }
                if (c + 4 < c1) {
                    #pragma unroll
                    for (int u = 0; u < 4; ++u) {
                        const int lo = (i0 + c + 4 + u) * D_ + og;
                        pL[u] = ld2(Wlo + lo);
                        pH[u] = ld2(Whi + lo);
                    }
                }
                #pragma unroll
                for (int u = 0; u < 4; ++u) {
                    const int i = i0 + c + u;
                    const float xv = scat[i];
                    const float4* mr = reinterpret_cast<const float4*>(sM[i]);
                    const float4 m0 = mr[0], m1 = mr[1], m2 = mr[2], m3 = mr[3];
                    accC0 = fmaf(xv, cL[u].x, accC0);
                    accC1 = fmaf(xv, cL[u].y, accC1);
                    const float mv[K_] = {m0.x,m0.y,m0.z,m0.w, m1.x,m1.y,m1.z,m1.w,
                                          m2.x,m2.y,m2.z,m2.w, m3.x,m3.y,m3.z,m3.w};
                    #pragma unroll
                    for (int j = 0; j < K_; ++j) {
                        accJ0[j] = fmaf(mv[j], cH[u].x, accJ0[j]);
                        accJ1[j] = fmaf(mv[j], cH[u].y, accJ1[j]);
                    }
                }
            }
        };

        // ================= PHASE 0 =================
        if (isA) {
            // q = x @ Wq + bq over my i-half
            float q0 = 0.f, q1 = 0.f;
            const int i0 = ih << 7;
            for (int c = 0; c < 128; c += 8) {
                float2 w[8];
                #pragma unroll
                for (int u = 0; u < 8; ++u) w[u] = ld2(Wq + (i0 + c + u) * D_ + og);
                #pragma unroll
                for (int u = 0; u < 8; ++u) {
                    const float xv = scat[i0 + c + u];
                    q0 = fmaf(xv, w[u].x, q0);
                    q1 = fmaf(xv, w[u].y, q1);
                }
            }
            q0 += __shfl_xor_sync(0xffffffffu, q0, 1);
            q1 += __shfl_xor_sync(0xffffffffu, q1, 1);
            q0 += bqv.x; q1 += bqv.y;
            if (ih == 0) { sQ[og] = q0; sQ[og + 1] = q1; }
            else st_peer_f64(peer_addr(smem_u32(&sQ[og]), peer), q0, q1);
        }
        gemm_chunk(0, 44);
        cluster_sync_();   // B0: full q visible in both CTAs

        // ================= PHASE 1 =================
        if (isA) {
            // Kvec: warp-per-row, lanes over o (coalesced)
            const float4 q4lo = reinterpret_cast<const float4*>(sQ)[lane];
            const float4 q4hi = reinterpret_cast<const float4*>(sQ)[lane + 32];
            for (int r = wid; r < 128; r += 4) {
                const float* wr = Wk + (size_t)((int)rank * 128 + r) * D_;
                const float4 wlo = reinterpret_cast<const float4*>(wr)[lane];
                const float4 whi = reinterpret_cast<const float4*>(wr)[lane + 32];
                float a = wlo.x * q4lo.x;
                a = fmaf(wlo.y, q4lo.y, a);
                a = fmaf(wlo.z, q4lo.z, a);
                a = fmaf(wlo.w, q4lo.w, a);
                a = fmaf(whi.x, q4hi.x, a);
                a = fmaf(whi.y, q4hi.y, a);
                a = fmaf(whi.z, q4hi.z, a);
                a = fmaf(whi.w, q4hi.w, a);
                #pragma unroll
                for (int off = 16; off; off >>= 1)
                    a += __shfl_xor_sync(0xffffffffu, a, off);
                if (lane == 0) sKv[r] = a;
            }
            barA();
            {
                const int gi = (int)rank * 128 + gt;
                const float kv = sKv[gt];
                const float4* mr = reinterpret_cast<const float4*>(sM[gi]);
                const float4 m0 = mr[0], m1 = mr[1], m2 = mr[2], m3 = mr[3];
                const float mv[K_] = {m0.x,m0.y,m0.z,m0.w, m1.x,m1.y,m1.z,m1.w,
                                      m2.x,m2.y,m2.z,m2.w, m3.x,m3.y,m3.z,m3.w};
                float p[K_];
                #pragma unroll
                for (int j = 0; j < K_; ++j) p[j] = mv[j] * kv;
                #pragma unroll
                for (int off = 1; off < 32; off <<= 1) {
                    #pragma unroll
                    for (int j = 0; j < K_; ++j)
                        p[j] += __shfl_xor_sync(0xffffffffu, p[j], off);
                }
                if (lane == 0) {
                    #pragma unroll
                    for (int j = 0; j < K_; ++j) sLP[wid][j] = p[j];
                }
            }
            barA();
            if (tid < K_) {
                const float s = sLP[0][tid] + sLP[1][tid] + sLP[2][tid] + sLP[3][tid];
                sLoc[tid] = s;
                st_peer_f32(peer_addr(smem_u32(&eL[tid]), peer), s);
            }
        }
        gemm_chunk(44, 88);
        cluster_sync_();   // B1: logit halves exchanged

        // ================= PHASE 2 =================
        if (isA) {
            if (tid < K_) {
                float l = (sLoc[tid] + eL[tid]) * 0.0625f;
                float mx = l;
                #pragma unroll
                for (int off = 8; off; off >>= 1) mx = fmaxf(mx, __shfl_xor_sync(0xffffu, mx, off, 16));
                const float e = expf(l - mx);
                float s = e;
                #pragma unroll
                for (int off = 8; off; off >>= 1) s += __shfl_xor_sync(0xffffu, s, off, 16);
                const float a = e / s;
                sAttn[tid] = a;
                if (tid == 0) sNov = 1.f - 1.f / s;
                const float pr = MOMC * sPers[tid] + (1.f - MOMC) * a;
                sPers[tid] = pr;
                float el = -4.f * pr, em = el;
                #pragma unroll
                for (int off = 8; off; off >>= 1) em = fmaxf(em, __shfl_xor_sync(0xffffu, em, off, 16));
                const float ee = expf(el - em);
                float es = ee;
                #pragma unroll
                for (int off = 8; off; off >>= 1) es += __shfl_xor_sync(0xffffu, es, off, 16);
                sEvict[tid] = ee / es;
            }
            barA();
            #pragma unroll
            for (int h = 0; h < 2; ++h) {
                const int f = gt + h * 128;
                const float4* mr = reinterpret_cast<const float4*>(sM[f]);
                const float4 m0 = mr[0], m1 = mr[1], m2 = mr[2], m3 = mr[3];
                const float mv[K_] = {m0.x,m0.y,m0.z,m0.w, m1.x,m1.y,m1.z,m1.w,
                                      m2.x,m2.y,m2.z,m2.w, m3.x,m3.y,m3.z,m3.w};
                float acc = 0.f;
                #pragma unroll
                for (int j = 0; j < K_; ++j) acc = fmaf(sAttn[j], mv[j], acc);
                sMbar[f] = acc;
            }
            barA();
            float r0 = 0.f, r1 = 0.f;
            const int i0 = ih << 7;
            for (int c = 0; c < 128; c += 8) {
                float2 w[8];
                #pragma unroll
                for (int u = 0; u < 8; ++u) w[u] = ld2(Wv + (i0 + c + u) * D_ + og);
                #pragma unroll
                for (int u = 0; u < 8; ++u) {
                    const float mb = sMbar[i0 + c + u];
                    r0 = fmaf(mb, w[u].x, r0);
                    r1 = fmaf(mb, w[u].y, r1);
                }
            }
            r0 += __shfl_xor_sync(0xffffffffu, r0, 1);
            r1 += __shfl_xor_sync(0xffffffffu, r1, 1);
            r0 += bvv.x; r1 += bvv.y;
            if (ih == 0) { scat[D_ + og] = r0; scat[D_ + og + 1] = r1; }
            else st_peer_f64(peer_addr(smem_u32(&scat[D_ + og]), peer), r0, r1);
        }
        gemm_chunk(88, 128);
        // cross-ih pair reduce (both lanes end with full sums)
        accC0 += __shfl_xor_sync(0xffffffffu, accC0, 1);
        accC1 += __shfl_xor_sync(0xffffffffu, accC1, 1);
        #pragma unroll
        for (int j = 0; j < K_; ++j) {
            accJ0[j] += __shfl_xor_sync(0xffffffffu, accJ0[j], 1);
            accJ1[j] += __shfl_xor_sync(0xffffffffu, accJ1[j], 1);
        }
        if (isA) {
            // erase sigmoid: each lane its own row (og + ih)
            const float bc = ih ? biasC1 : biasC0;
            const float cc = ih ? accC1 : accC0;
            float e[K_];
            #pragma unroll
            for (int j = 0; j < K_; ++j)
                e[j] = sigmf((ih ? accJ1[j] : accJ0[j]) + cc + bc);
            float4* er = reinterpret_cast<float4*>(sE[op * 2 + ih]);
            er[0] = make_float4(e[0],  e[1],  e[2],  e[3]);
            er[1] = make_float4(e[4],  e[5],  e[6],  e[7]);
            er[2] = make_float4(e[8],  e[9],  e[10], e[11]);
            er[3] = make_float4(e[12], e[13], e[14], e[15]);
        } else {
            // write-candidate gelu: each lane its own row; gstat butterfly
            const float bc = ih ? biasC1 : biasC0;
            const float cc = ih ? accC1 : accC0;
            float g[K_], gs[K_], gq[K_];
            #pragma unroll
            for (int j = 0; j < K_; ++j) {
                g[j]  = geluf((ih ? accJ1[j] : accJ0[j]) + cc + bc);
                gs[j] = g[j];
                gq[j] = g[j] * g[j];
            }
            #pragma unroll
            for (int off = 1; off < 32; off <<= 1) {
                #pragma unroll
                for (int j = 0; j < K_; ++j) {
                    gs[j] += __shfl_xor_sync(0xffffffffu, gs[j], off);
                    gq[j] += __shfl_xor_sync(0xffffffffu, gq[j], off);
                }
            }
            if (lane == 0) {
                #pragma unroll
                for (int j = 0; j < K_; ++j) {
                    sGP[wid - 4][j] = gs[j];
                    sGP[wid - 4][K_ + j] = gq[j];
                }
            }
            float4* gr = reinterpret_cast<float4*>(sG[op * 2 + ih]);
            gr[0] = make_float4(g[0],  g[1],  g[2],  g[3]);
            gr[1] = make_float4(g[4],  g[5],  g[6],  g[7]);
            gr[2] = make_float4(g[8],  g[9],  g[10], g[11]);
            gr[3] = make_float4(g[12], g[13], g[14], g[15]);
            barB();
            if (gt < 2 * K_) {
                const float s = sGP[0][gt] + sGP[1][gt] + sGP[2][gt] + sGP[3][gt];
                sGloc[gt] = s;
                st_peer_f32(peer_addr(smem_u32(&eG[gt]), peer), s);
            }
        }
        cluster_sync_();   // B2: cat complete + gstats exchanged

        // ================= PHASE 3 =================
        if (tid < K_) {
            const float gsum = sGloc[tid] + eG[tid];
            const float gsq  = sGloc[K_ + tid] + eG[K_ + tid];
            const float mean = gsum * (1.f / D_);
            const float var  = gsq * (1.f / D_) - mean * mean;
            sMean[tid] = mean;
            sRstd[tid] = rsqrtf(var + EPSLN);
        }
        // fu / wg1: A does cat[0..255], B does cat[256..511]; double-buffered
        float af0 = 0.f, af1 = 0.f, ag0 = 0.f, ag1 = 0.f;
        {
            const int base = isA ? 0 : 256;
            const int c0 = base + (ih << 7);
            float2 pF[4], pG[4];
            #pragma unroll
            for (int u = 0; u < 4; ++u) {
                const int wix = (c0 + u) * D_ + og;
                pF[u] = ld2(fuW + wix);
                pG[u] = ld2(wg1W + wix);
            }
            for (int c = 0; c < 128; c += 4) {
                float2 cF[4], cG[4];
                #pragma unroll
                for (int u = 0; u < 4; ++u) { cF[u] = pF[u]; cG[u] = pG[u]; }
                if (c + 4 < 128) {
                    #pragma unroll
                    for (int u = 0; u < 4; ++u) {
                        const int wix = (c0 + c + 4 + u) * D_ + og;
                        pF[u] = ld2(fuW + wix);
                        pG[u] = ld2(wg1W + wix);
                    }
                }
                #pragma unroll
                for (int u = 0; u < 4; ++u) {
                    const float cv = scat[c0 + c + u];
                    af0 = fmaf(cv, cF[u].x, af0); af1 = fmaf(cv, cF[u].y, af1);
                    ag0 = fmaf(cv, cG[u].x, ag0); ag1 = fmaf(cv, cG[u].y, ag1);
                }
            }
            af0 += __shfl_xor_sync(0xffffffffu, af0, 1);
            af1 += __shfl_xor_sync(0xffffffffu, af1, 1);
            ag0 += __shfl_xor_sync(0xffffffffu, ag0, 1);
            ag1 += __shfl_xor_sync(0xffffffffu, ag1, 1);
        }
        if (!isA && ih == 0) {
            sFB[op][0] = af0; sFB[op][1] = af1; sFB[op][2] = ag0; sFB[op][3] = ag1;
        }
        __syncthreads();
        float hf0 = 0.f, hf1 = 0.f;
        if (isA) {
            af0 += sFB[op][0]; af1 += sFB[op][1];
            ag0 += sFB[op][2]; ag1 += sFB[op][3];
            hf0 = geluf(af0 + fubv.x);
            hf1 = geluf(af1 + fubv.y);
            const float hg0 = geluf(ag0 + wg1bv.x);
            const float hg1 = geluf(ag1 + wg1bv.y);
            float a0 = hf0 + hf1;
            float a1 = hf0 * hf0 + hf1 * hf1;
            float a2 = hg0 * wg2wv.x + hg1 * wg2wv.y;
            #pragma unroll
            for (int off = 2; off <= 16; off <<= 1) {
                a0 += __shfl_xor_sync(0xffffffffu, a0, off);
                a1 += __shfl_xor_sync(0xffffffffu, a1, off);
                a2 += __shfl_xor_sync(0xffffffffu, a2, off);
            }
            if (lane == 0) { sBR[wid][0] = a0; sBR[wid][1] = a1; sBR[wid][2] = a2; }
            barA();
            if (tid < 3) {
                const float s = sBR[0][tid] + sBR[1][tid] + sBR[2][tid] + sBR[3][tid];
                sF[tid] = s;
                st_peer_f32(peer_addr(smem_u32(&eF[tid]), peer), s);
            }
        }
        cluster_sync_();   // B3: fu-LN + wg2 partials exchanged

        // ================= PHASE 4 =================
        const float gw = sigmf(sF[2] + eF[2] + wg2b0) * sNov;
        if (tid < K_) sPers[tid] += sEvict[tid] * gw * 0.1f;

        float u0 = 0.f, u1 = 0.f;
        if (isA) {
            const float fsum = sF[0] + eF[0], fsq = sF[1] + eF[1];
            const float fmn = fsum * (1.f / D_);
            const float fvr = fsq * (1.f / D_) - fmn * fmn;
            const float frs = rsqrtf(fvr + EPSLN);
            const float outt0 = (hf0 - fmn) * frs * fulngv.x + fulnbv.x;
            const float outt1 = (hf1 - fmn) * frs * fulngv.y + fulnbv.y;
            u0 = outt0 + scat[og];
            u1 = outt1 + scat[og + 1];
            float b0 = u0 + u1;
            float b1 = u0 * u0 + u1 * u1;
            #pragma unroll
            for (int off = 2; off <= 16; off <<= 1) {
                b0 += __shfl_xor_sync(0xffffffffu, b0, off);
                b1 += __shfl_xor_sync(0xffffffffu, b1, off);
            }
            if (lane == 0) { sBR[wid][0] = b0; sBR[wid][1] = b1; }
            barA();
            if (tid < 2) {
                const float s = sBR[0][tid] + sBR[1][tid] + sBR[2][tid] + sBR[3][tid];
                sU[tid] = s;
                st_peer_f32(peer_addr(smem_u32(&eU[tid]), peer), s);
            }
        } else {
            // M update: one row per B thread (local + peer mirror)
            float nm[K_];
            #pragma unroll
            for (int j = 0; j < K_; ++j) {
                const float al = gw * sEvict[j];
                const float wr = (sG[gt][j] - sMean[j]) * sRstd[j] * cgB + cbB;
                nm[j] = sM[grow][j] * (1.f - al * sE[gt][j]) + al * wr;
            }
            float4* rowp = reinterpret_cast<float4*>(sM[grow]);
            rowp[0] = make_float4(nm[0],  nm[1],  nm[2],  nm[3]);
            rowp[1] = make_float4(nm[4],  nm[5],  nm[6],  nm[7]);
            rowp[2] = make_float4(nm[8],  nm[9],  nm[10], nm[11]);
            rowp[3] = make_float4(nm[12], nm[13], nm[14], nm[15]);
            uint32_t ra = peer_addr(smem_u32(&sM[grow][0]), peer);
            st_peer_f128(ra,      make_float4(nm[0],  nm[1],  nm[2],  nm[3]));
            st_peer_f128(ra + 16, make_float4(nm[4],  nm[5],  nm[6],  nm[7]));
            st_peer_f128(ra + 32, make_float4(nm[8],  nm[9],  nm[10], nm[11]));
            st_peer_f128(ra + 48, make_float4(nm[12], nm[13], nm[14], nm[15]));
        }
        cluster_sync_();   // B4: out-LN partials + peer M halves visible

        if (isA && ih == 0) {
            const float usum = sU[0] + eU[0], usq = sU[1] + eU[1];
            const float um = usum * (1.f / D_);
            const float uv = usq * (1.f / D_) - um * um;
            const float rr = rsqrtf(uv + EPSLN);
            float* po = out + ((size_t)t * B_ + b) * D_ + og;
            po[0] = (u0 - um) * rr * ongv.x + onbv.x;
            po[1] = (u1 - um) * rr * ongv.y + onbv.y;
        }
    }

    // proto = transpose(M, (1,0,2)) : [K, B, d]
    if (isA && ih == 0) {
        #pragma unroll
        for (int j = 0; j < K_; ++j) {
            out[(size_t)S_ * B_ * D_ + ((size_t)j * B_ + b) * D_ + og]     = sM[og][j];
            out[(size_t)S_ * B_ * D_ + ((size_t)j * B_ + b) * D_ + og + 1] = sM[og + 1][j];
        }
    }
}

extern "C" void kernel_launch(void* const* d_in, const int* in_sizes, int n_in,
                              void* d_out, int out_size) {
    (void)in_sizes; (void)n_in; (void)out_size;
    memunit_kernel<<<2 * B_, NT>>>(
        (const float*)d_in[0],  (const float*)d_in[1],
        (const float*)d_in[2],  (const float*)d_in[3],
        (const float*)d_in[4],  (const float*)d_in[5],
        (const float*)d_in[6],  (const float*)d_in[7],
        (const float*)d_in[8],  (const float*)d_in[9],
        (const float*)d_in[10], (const float*)d_in[11],
        (const float*)d_in[12], (const float*)d_in[13],
        (const float*)d_in[14], (const float*)d_in[15],
        (const float*)d_in[16], (const float*)d_in[17],
        (const float*)d_in[18], (const float*)d_in[19],
        (const float*)d_in[20], (const float*)d_in[21],
        (const float*)d_in[22], (const float*)d_in[23],
        (float*)d_out);
}